// round 13
// baseline (speedup 1.0000x reference)
#include <cuda_runtime.h>
#include <cuda_fp16.h>
#include <cstdint>

// ---------------- problem constants ----------------
#define B_DIM  1024
#define K_DIM  256
#define UNITS  32
#define KU     8192          // K_DIM*UNITS
#define KRED   2048          // 1024 AR + 1024 MA reduction cols

#define BM 128               // b per CTA
#define BN 128               // j per CTA

// HMMA tiling (R6, validated)
#define HBK 32
#define HSTEPS (KRED / HBK)  // 64
#define ABYTES 8192
#define BUFBYTES 16384

// FFMA tiling (R2, validated)
#define FBK 16

// unit split: 23 HMMA units, 9 FFMA units
#define NF 9

// ---------------- helpers ----------------
__device__ __forceinline__ uint32_t smem_u32(const void* p) {
    uint32_t a;
    asm("{ .reg .u64 t; cvta.to.shared.u64 t, %1; cvt.u32.u64 %0, t; }" : "=r"(a) : "l"(p));
    return a;
}
__device__ __forceinline__ uint32_t pack_f16x2(float lo, float hi) {
    uint32_t r; asm("cvt.rn.f16x2.f32 %0, %1, %2;" : "=r"(r) : "f"(hi), "f"(lo)); return r;
}
__device__ __forceinline__ void sts32(uint32_t a, uint32_t v) {
    asm volatile("st.shared.b32 [%0], %1;" :: "r"(a), "r"(v) : "memory");
}
__device__ __forceinline__ void sts128(uint32_t a, uint32_t x, uint32_t y, uint32_t z, uint32_t w) {
    asm volatile("st.shared.v4.b32 [%0], {%1,%2,%3,%4};" :: "r"(a), "r"(x), "r"(y), "r"(z), "r"(w) : "memory");
}
__device__ __forceinline__ void ldsm4(uint32_t& r0, uint32_t& r1, uint32_t& r2, uint32_t& r3, uint32_t addr) {
    asm volatile("ldmatrix.sync.aligned.m8n8.x4.shared.b16 {%0,%1,%2,%3}, [%4];"
                 : "=r"(r0), "=r"(r1), "=r"(r2), "=r"(r3) : "r"(addr));
}
__device__ __forceinline__ void mma_f16(float& d0, float& d1, float& d2, float& d3,
                                        uint32_t a0, uint32_t a1, uint32_t a2, uint32_t a3,
                                        uint32_t b0, uint32_t b1) {
    asm volatile("mma.sync.aligned.m16n8k16.row.col.f32.f16.f16.f32 "
                 "{%0,%1,%2,%3}, {%4,%5,%6,%7}, {%8,%9}, {%0,%1,%2,%3};"
                 : "+f"(d0), "+f"(d1), "+f"(d2), "+f"(d3)
                 : "r"(a0), "r"(a1), "r"(a2), "r"(a3), "r"(b0), "r"(b1));
}

// ================= hybrid kernel =================
// Per unit u: D[b, j] = sum_r X_u[b,r] * W_u[r,j],  r in [0,2048)
//   r <  1024: X = inputs[b*1024 + r];  W = wkern[((p*32+u)*256+i)*256 + j], i=r>>2, p=r&3
//   r >= 1024: r'=r-1024, i=r'>>2, q=r'&3
//              X = state[b*32768 + i*128 + u*4 + q]; W = rkern[((q*32+u)*256+i)*256 + j]
// Epilogue (both paths): out[o]=D; out_state[o*4..] = {D, state[o*4], state[o*4+1], state[o*4+2]}
// z-map: z 0..8 -> HMMA u=z; z 9..17 -> FFMA u=23+(z-9); z 18..31 -> HMMA u=z-9.
// (wave-1 bids 0..147 all-H, 148..295 all-F => per-SM H/F pairing => both pipes busy)
__global__ void __launch_bounds__(256, 2)
arma_hybrid_kernel(const float* __restrict__ inputs,
                   const float* __restrict__ state,
                   const float* __restrict__ wkern,
                   const float* __restrict__ rkern,
                   float* __restrict__ out,
                   float* __restrict__ out_state)
{
    __shared__ __align__(128) char smem_raw[2][BUFBYTES];   // 32KB, shared by both paths

    const int tid = threadIdx.x;
    const int z   = blockIdx.z;
    const int jn0 = blockIdx.x * BN;
    const int bm0 = blockIdx.y * BM;

    int u, isF;
    if (z < 9)       { u = z;            isF = 0; }
    else if (z < 18) { u = 23 + (z - 9); isF = 1; }
    else             { u = z - 9;        isF = 0; }

    if (isF) {
        // ================= FFMA path (R2 body, validated) =================
        float (*sA)[BM] = (float (*)[BM])(&smem_raw[0][0]);        // [16][128] 8KB
        float (*sB)[BN] = (float (*)[BN])(&smem_raw[0][ABYTES]);   // [16][128] 8KB
        const int tx = tid & 15;
        const int ty = tid >> 4;

        float acc[8][8];
        #pragma unroll
        for (int m = 0; m < 8; m++)
            #pragma unroll
            for (int n = 0; n < 8; n++) acc[m][n] = 0.f;

        for (int kt = 0; kt < KRED; kt += FBK) {
            #pragma unroll
            for (int l = 0; l < 2; l++) {
                int f  = tid + l * 256;
                int bl = f >> 2;
                int kc = (f & 3) * 4;
                int r  = kt + kc;
                int b  = bm0 + bl;
                float4 v;
                if (r < 1024) {
                    v = *(const float4*)(inputs + (size_t)b * 1024 + r);
                } else {
                    int i = (r - 1024) >> 2;
                    v = *(const float4*)(state + (size_t)b * 32768 + i * 128 + u * 4);
                }
                sA[kc + 0][bl] = v.x;
                sA[kc + 1][bl] = v.y;
                sA[kc + 2][bl] = v.z;
                sA[kc + 3][bl] = v.w;
            }
            #pragma unroll
            for (int l = 0; l < 2; l++) {
                int f  = tid + l * 256;
                int r  = f >> 5;
                int c4 = (f & 31) * 4;
                int rg = kt + r;
                const float* row;
                if (rg < 1024) {
                    int i = rg >> 2, p = rg & 3;
                    row = wkern + (((size_t)p * UNITS + u) * K_DIM + i) * K_DIM;
                } else {
                    int rp = rg - 1024;
                    int i = rp >> 2, q = rp & 3;
                    row = rkern + (((size_t)q * UNITS + u) * K_DIM + i) * K_DIM;
                }
                *(float4*)&sB[r][c4] = *(const float4*)(row + jn0 + c4);
            }
            __syncthreads();

            #pragma unroll
            for (int r = 0; r < FBK; r++) {
                float a[8], bb[8];
                #pragma unroll
                for (int m = 0; m < 8; m += 4)
                    *(float4*)&a[m] = *(const float4*)&sA[r][ty * 8 + m];
                #pragma unroll
                for (int n = 0; n < 8; n += 4)
                    *(float4*)&bb[n] = *(const float4*)&sB[r][tx * 8 + n];
                #pragma unroll
                for (int m = 0; m < 8; m++)
                    #pragma unroll
                    for (int n = 0; n < 8; n++)
                        acc[m][n] = fmaf(a[m], bb[n], acc[m][n]);
            }
            __syncthreads();
        }

        // fused epilogue
        #pragma unroll
        for (int m = 0; m < 8; m++) {
            const int b = bm0 + ty * 8 + m;
            #pragma unroll
            for (int n = 0; n < 8; n++) {
                const int j = jn0 + tx * 8 + n;
                const size_t o = (size_t)b * KU + (size_t)j * UNITS + u;
                float v = acc[m][n];
                float4 s4 = *(const float4*)(state + o * 4);
                out[o] = v;
                *(float4*)(out_state + o * 4) = make_float4(v, s4.x, s4.y, s4.z);
            }
        }
        return;
    }

    // ================= HMMA path (R6 body, validated) =================
    const int wid = tid >> 5;
    const int lid = tid & 31;
    const uint32_t smem0 = smem_u32(smem_raw);

    // A (X) staging: row = tid>>1, k-half 16 = tid&1
    const int arow = tid >> 1;
    const int ah   = tid & 1;
    const int bg   = bm0 + arow;
    const int ar3  = arow & 3;
    const uint32_t aOff0 = (uint32_t)(arow * 64) + (uint32_t)(((ah * 2 + 0) ^ ar3) << 4);
    const uint32_t aOff1 = (uint32_t)(arow * 64) + (uint32_t)(((ah * 2 + 1) ^ ar3) << 4);

    // B (W) staging
    const int ahat = lid >> 3;
    const int bhat = lid & 7;
    const int kq   = wid & 3;
    const int jhi  = wid >> 2;
    const int kp   = kq * 4 + ahat;
    const int p0   = 2 * (kp & 1);
    const int ipo  = kp >> 1;
    const int j0s  = jhi * 8 + bhat;
    const int kg   = kp >> 2;
    const uint32_t wOff = (uint32_t)ABYTES + (uint32_t)(j0s * 64)
                        + (uint32_t)(((kg ^ (j0s & 3)) << 4) + (kp & 3) * 4);

    // fragment maps
    const int wm = wid >> 2;
    const int wn = wid & 3;
    const int aRow  = wm * 64 + (lid & 15);
    const int aHi   = lid >> 4;
    const int bRowL = wn * 32 + (lid & 7) + ((lid >> 4) << 3);
    const int bHi   = (lid >> 3) & 1;
    const int l3    = lid & 3;

    float d[4][4][4];
    #pragma unroll
    for (int mi = 0; mi < 4; mi++)
        #pragma unroll
        for (int ni = 0; ni < 4; ni++)
            #pragma unroll
            for (int r = 0; r < 4; r++) d[mi][ni][r] = 0.f;

    float4 xa[4];

    auto load_x = [&](int step) {
        const int kt = step * HBK;
        if (kt < 1024) {
            const float4* src = (const float4*)(inputs + (size_t)bg * 1024 + kt + ah * 16);
            #pragma unroll
            for (int c = 0; c < 4; c++) xa[c] = src[c];
        } else {
            const float* sp = state + (size_t)bg * 32768
                            + (size_t)(((kt - 1024) >> 2) + ah * 4) * 128 + u * 4;
            #pragma unroll
            for (int c = 0; c < 4; c++) xa[c] = *(const float4*)(sp + c * 128);
        }
    };
    auto sts_a = [&](int buf) {
        const uint32_t base = smem0 + (uint32_t)buf * BUFBYTES;
        sts128(base + aOff0,
               pack_f16x2(xa[0].x, xa[0].y), pack_f16x2(xa[0].z, xa[0].w),
               pack_f16x2(xa[1].x, xa[1].y), pack_f16x2(xa[1].z, xa[1].w));
        sts128(base + aOff1,
               pack_f16x2(xa[2].x, xa[2].y), pack_f16x2(xa[2].z, xa[2].w),
               pack_f16x2(xa[3].x, xa[3].y), pack_f16x2(xa[3].z, xa[3].w));
    };
    auto stage_w = [&](int step, int buf) {
        const int kt   = step * HBK;
        const int half = (kt >= 1024);
        const float* wb = half ? rkern : wkern;
        const int i0 = (((half ? kt - 1024 : kt)) >> 2) + ipo;
        const float* r0p = wb + (((size_t)(p0 * UNITS + u) * K_DIM + i0) * K_DIM) + jn0 + j0s;
        const float* r1p = wb + (((size_t)((p0 + 1) * UNITS + u) * K_DIM + i0) * K_DIM) + jn0 + j0s;
        float w0[8], w1[8];
        #pragma unroll
        for (int mh = 0; mh < 8; mh++) { w0[mh] = r0p[mh * 16]; w1[mh] = r1p[mh * 16]; }
        const uint32_t wdst = smem0 + (uint32_t)buf * BUFBYTES + wOff;
        #pragma unroll
        for (int mh = 0; mh < 8; mh++)
            sts32(wdst + (uint32_t)(mh * 1024), pack_f16x2(w0[mh], w1[mh]));
    };

    load_x(0);
    sts_a(0);
    stage_w(0, 0);
    __syncthreads();

    for (int s = 0; s < HSTEPS; s++) {
        const int cur = s & 1;
        if (s + 1 < HSTEPS) load_x(s + 1);

        const uint32_t sA = smem0 + (uint32_t)cur * BUFBYTES;
        const uint32_t sB = sA + ABYTES;

        #pragma unroll
        for (int kk = 0; kk < 2; kk++) {
            uint32_t a[4][4];
            #pragma unroll
            for (int mi = 0; mi < 4; mi++) {
                uint32_t addr = sA + (uint32_t)((aRow + mi * 16) * 64)
                              + (uint32_t)((((kk * 2 + aHi) ^ l3)) << 4);
                ldsm4(a[mi][0], a[mi][1], a[mi][2], a[mi][3], addr);
            }
            uint32_t bf[4][2];
            #pragma unroll
            for (int ni2 = 0; ni2 < 2; ni2++) {
                uint32_t addr = sB + (uint32_t)((bRowL + ni2 * 16) * 64)
                              + (uint32_t)((((kk * 2 + bHi) ^ l3)) << 4);
                uint32_t r0, r1, r2, r3;
                ldsm4(r0, r1, r2, r3, addr);
                bf[ni2 * 2][0] = r0;      bf[ni2 * 2][1] = r1;
                bf[ni2 * 2 + 1][0] = r2;  bf[ni2 * 2 + 1][1] = r3;
            }
            #pragma unroll
            for (int mi = 0; mi < 4; mi++)
                #pragma unroll
                for (int ni = 0; ni < 4; ni++)
                    mma_f16(d[mi][ni][0], d[mi][ni][1], d[mi][ni][2], d[mi][ni][3],
                            a[mi][0], a[mi][1], a[mi][2], a[mi][3],
                            bf[ni][0], bf[ni][1]);
        }

        if (s + 1 < HSTEPS) {
            sts_a(cur ^ 1);
            stage_w(s + 1, cur ^ 1);
        }
        __syncthreads();
    }

    // fused epilogue
    const int crow = lid >> 2;
    const int ccol = 2 * (lid & 3);
    #pragma unroll
    for (int mi = 0; mi < 4; mi++) {
        const int b0 = bm0 + wm * 64 + mi * 16 + crow;
        #pragma unroll
        for (int ni = 0; ni < 4; ni++) {
            const int j0 = jn0 + wn * 32 + ni * 8 + ccol;
            #pragma unroll
            for (int e = 0; e < 4; e++) {
                const int bb = b0 + (e >> 1) * 8;
                const int jj = j0 + (e & 1);
                const size_t o = (size_t)bb * KU + (size_t)jj * UNITS + u;
                const float v = d[mi][ni][e];
                float4 s4 = *(const float4*)(state + o * 4);
                out[o] = v;
                *(float4*)(out_state + o * 4) = make_float4(v, s4.x, s4.y, s4.z);
            }
        }
    }
}

extern "C" void kernel_launch(void* const* d_in, const int* in_sizes, int n_in,
                              void* d_out, int out_size)
{
    const float* inputs = (const float*)d_in[0];
    const float* state  = (const float*)d_in[1];
    const float* wkern  = (const float*)d_in[2];
    const float* rkern  = (const float*)d_in[3];

    float* out       = (float*)d_out;
    float* out_state = (float*)d_out + (size_t)B_DIM * KU;

    dim3 grid(K_DIM / BN, B_DIM / BM, UNITS);   // (2, 8, 32) = 512 CTAs
    arma_hybrid_kernel<<<grid, 256>>>(inputs, state, wkern, rkern, out, out_state);
}

// round 17
// speedup vs baseline: 1.1563x; 1.1563x over previous
#include <cuda_runtime.h>
#include <cuda_fp16.h>
#include <cstdint>

// ---------------- problem constants ----------------
#define B_DIM  1024
#define K_DIM  256
#define UNITS  32
#define KU     8192          // K_DIM*UNITS
#define KRED   2048          // 1024 AR + 1024 MA reduction cols

// ---------------- tiling ----------------
#define BM 128               // b per CTA (MMA M)
#define BN 64                // j per CTA (MMA N)  -- halved vs R6 for occupancy
#define BK 32                // K per stage
#define NSTEPS (KRED / BK)   // 64
// 8 warps 4(m) x 2(n); warp tile 32(m) x 32(n); fp16 m16n8k16

// smem per buffer: A 128x32 fp16 (8KB) + B 64x32 fp16 (4KB) = 12KB; 2 buffers = 24KB
#define ABYTES 8192
#define BUFBYTES 12288

// ---------------- helpers ----------------
__device__ __forceinline__ uint32_t smem_u32(const void* p) {
    uint32_t a;
    asm("{ .reg .u64 t; cvta.to.shared.u64 t, %1; cvt.u32.u64 %0, t; }" : "=r"(a) : "l"(p));
    return a;
}
__device__ __forceinline__ uint32_t pack_f16x2(float lo, float hi) {
    uint32_t r; asm("cvt.rn.f16x2.f32 %0, %1, %2;" : "=r"(r) : "f"(hi), "f"(lo)); return r;
}
__device__ __forceinline__ void sts32(uint32_t a, uint32_t v) {
    asm volatile("st.shared.b32 [%0], %1;" :: "r"(a), "r"(v) : "memory");
}
__device__ __forceinline__ void sts128(uint32_t a, uint32_t x, uint32_t y, uint32_t z, uint32_t w) {
    asm volatile("st.shared.v4.b32 [%0], {%1,%2,%3,%4};" :: "r"(a), "r"(x), "r"(y), "r"(z), "r"(w) : "memory");
}
__device__ __forceinline__ void ldsm4(uint32_t& r0, uint32_t& r1, uint32_t& r2, uint32_t& r3, uint32_t addr) {
    asm volatile("ldmatrix.sync.aligned.m8n8.x4.shared.b16 {%0,%1,%2,%3}, [%4];"
                 : "=r"(r0), "=r"(r1), "=r"(r2), "=r"(r3) : "r"(addr));
}
__device__ __forceinline__ void mma_f16(float& d0, float& d1, float& d2, float& d3,
                                        uint32_t a0, uint32_t a1, uint32_t a2, uint32_t a3,
                                        uint32_t b0, uint32_t b1) {
    asm volatile("mma.sync.aligned.m16n8k16.row.col.f32.f16.f16.f32 "
                 "{%0,%1,%2,%3}, {%4,%5,%6,%7}, {%8,%9}, {%0,%1,%2,%3};"
                 : "+f"(d0), "+f"(d1), "+f"(d2), "+f"(d3)
                 : "r"(a0), "r"(a1), "r"(a2), "r"(a3), "r"(b0), "r"(b1));
}

// ---------------- GEMM kernel ----------------
// Per unit u: D[b, j] = sum_r X_u[b,r] * W_u[r,j],  r in [0,2048)
//   r <  1024: X = inputs[b*1024 + r];  W = wkern[((p*32+u)*256+i)*256 + j], i=r>>2, p=r&3
//   r >= 1024: r'=r-1024, i=r'>>2, q=r'&3
//              X = state[b*32768 + i*128 + u*4 + q]; W = rkern[((q*32+u)*256+i)*256 + j]
// smem fp16, 64B rows (32 k elems), swizzle: (row,k) ->
//   row*64 + (((k>>3) ^ (row&3))<<4) + (k&7)*2          (R6-validated)
// Epilogue fused with shift: out[o]=D; out_state[4o..] = {D, state[4o], state[4o+1], state[4o+2]}
__global__ void __launch_bounds__(256, 3)
arma_hmma_kernel(const float* __restrict__ inputs,
                 const float* __restrict__ state,
                 const float* __restrict__ wkern,
                 const float* __restrict__ rkern,
                 float* __restrict__ out,
                 float* __restrict__ out_state)
{
    __shared__ __align__(128) char smem[2][BUFBYTES];

    const int tid = threadIdx.x;
    const int wid = tid >> 5;
    const int lid = tid & 31;
    const int u   = blockIdx.z;
    const int jn0 = blockIdx.x * BN;
    const int bm0 = blockIdx.y * BM;

    const uint32_t smem0 = smem_u32(smem);

    // ---- A (X) staging map (unchanged from R6): row = tid>>1, k-half 16 = tid&1 ----
    const int arow = tid >> 1;
    const int ah   = tid & 1;
    const int bg   = bm0 + arow;
    const int ar3  = arow & 3;
    const uint32_t aOff0 = (uint32_t)(arow * 64) + (uint32_t)(((ah * 2 + 0) ^ ar3) << 4);
    const uint32_t aOff1 = (uint32_t)(arow * 64) + (uint32_t)(((ah * 2 + 1) ^ ar3) << 4);

    // ---- B (W) staging map (R6 formulas, 64 rows: mh<4) ----
    const int ahat = lid >> 3;          // 0..3
    const int bhat = lid & 7;
    const int kq   = wid & 3;
    const int jhi  = wid >> 2;
    const int kp   = kq * 4 + ahat;     // k-pair 0..15 (k = 2kp, 2kp+1)
    const int p0   = 2 * (kp & 1);      // plane of k0
    const int ipo  = kp >> 1;           // i offset within step
    const int j0s  = jhi * 8 + bhat;    // j low bits (mh adds *16, mh<4 -> j<64)
    const int kg   = kp >> 2;
    const uint32_t wOff = (uint32_t)ABYTES + (uint32_t)(j0s * 64)
                        + (uint32_t)(((kg ^ (j0s & 3)) << 4) + (kp & 3) * 4);

    // ---- fragment maps: warp grid 4(m) x 2(n), warp tile 32x32 ----
    const int wm = wid >> 1;            // 0..3
    const int wn = wid & 1;             // 0..1
    const int aRow  = wm * 32 + (lid & 15);
    const int aHi   = lid >> 4;
    const int bRowL = wn * 32 + (lid & 7) + ((lid >> 4) << 3);
    const int bHi   = (lid >> 3) & 1;
    const int l3    = lid & 3;

    float d[2][4][4];
    #pragma unroll
    for (int mi = 0; mi < 2; mi++)
        #pragma unroll
        for (int ni = 0; ni < 4; ni++)
            #pragma unroll
            for (int r = 0; r < 4; r++) d[mi][ni][r] = 0.f;

    float4 xa[4];

    auto load_x = [&](int step) {
        const int kt = step * BK;
        if (kt < 1024) {
            const float4* src = (const float4*)(inputs + (size_t)bg * 1024 + kt + ah * 16);
            #pragma unroll
            for (int c = 0; c < 4; c++) xa[c] = src[c];
        } else {
            const float* sp = state + (size_t)bg * 32768
                            + (size_t)(((kt - 1024) >> 2) + ah * 4) * 128 + u * 4;
            #pragma unroll
            for (int c = 0; c < 4; c++) xa[c] = *(const float4*)(sp + c * 128);
        }
    };
    auto sts_a = [&](int buf) {
        const uint32_t base = smem0 + (uint32_t)buf * BUFBYTES;
        sts128(base + aOff0,
               pack_f16x2(xa[0].x, xa[0].y), pack_f16x2(xa[0].z, xa[0].w),
               pack_f16x2(xa[1].x, xa[1].y), pack_f16x2(xa[1].z, xa[1].w));
        sts128(base + aOff1,
               pack_f16x2(xa[2].x, xa[2].y), pack_f16x2(xa[2].z, xa[2].w),
               pack_f16x2(xa[3].x, xa[3].y), pack_f16x2(xa[3].z, xa[3].w));
    };
    auto stage_w = [&](int step, int buf) {
        const int kt   = step * BK;
        const int half = (kt >= 1024);
        const float* wb = half ? rkern : wkern;
        const int i0 = (((half ? kt - 1024 : kt)) >> 2) + ipo;
        const float* r0p = wb + (((size_t)(p0 * UNITS + u) * K_DIM + i0) * K_DIM) + jn0 + j0s;
        const float* r1p = wb + (((size_t)((p0 + 1) * UNITS + u) * K_DIM + i0) * K_DIM) + jn0 + j0s;
        float w0[4], w1[4];
        #pragma unroll
        for (int mh = 0; mh < 4; mh++) { w0[mh] = r0p[mh * 16]; w1[mh] = r1p[mh * 16]; }
        const uint32_t wdst = smem0 + (uint32_t)buf * BUFBYTES + wOff;
        #pragma unroll
        for (int mh = 0; mh < 4; mh++)
            sts32(wdst + (uint32_t)(mh * 1024), pack_f16x2(w0[mh], w1[mh]));
    };

    // ---- prologue ----
    load_x(0);
    sts_a(0);
    stage_w(0, 0);
    __syncthreads();

    for (int s = 0; s < NSTEPS; s++) {
        const int cur = s & 1;
        if (s + 1 < NSTEPS) load_x(s + 1);

        const uint32_t sA = smem0 + (uint32_t)cur * BUFBYTES;
        const uint32_t sB = sA + ABYTES;

        #pragma unroll
        for (int kk = 0; kk < 2; kk++) {
            uint32_t a[2][4];
            #pragma unroll
            for (int mi = 0; mi < 2; mi++) {
                uint32_t addr = sA + (uint32_t)((aRow + mi * 16) * 64)
                              + (uint32_t)((((kk * 2 + aHi) ^ l3)) << 4);
                ldsm4(a[mi][0], a[mi][1], a[mi][2], a[mi][3], addr);
            }
            uint32_t bf[4][2];
            #pragma unroll
            for (int ni2 = 0; ni2 < 2; ni2++) {
                uint32_t addr = sB + (uint32_t)((bRowL + ni2 * 16) * 64)
                              + (uint32_t)((((kk * 2 + bHi) ^ l3)) << 4);
                uint32_t r0, r1, r2, r3;
                ldsm4(r0, r1, r2, r3, addr);
                bf[ni2 * 2][0] = r0;      bf[ni2 * 2][1] = r1;
                bf[ni2 * 2 + 1][0] = r2;  bf[ni2 * 2 + 1][1] = r3;
            }
            #pragma unroll
            for (int mi = 0; mi < 2; mi++)
                #pragma unroll
                for (int ni = 0; ni < 4; ni++)
                    mma_f16(d[mi][ni][0], d[mi][ni][1], d[mi][ni][2], d[mi][ni][3],
                            a[mi][0], a[mi][1], a[mi][2], a[mi][3],
                            bf[ni][0], bf[ni][1]);
        }

        if (s + 1 < NSTEPS) {
            sts_a(cur ^ 1);          // other buffer fully consumed at step s-1
            stage_w(s + 1, cur ^ 1);
        }
        __syncthreads();
    }

    // ---- fused epilogue: out + out_state ----
    const int crow = lid >> 2;
    const int ccol = 2 * (lid & 3);
    #pragma unroll
    for (int mi = 0; mi < 2; mi++) {
        const int b0 = bm0 + wm * 32 + mi * 16 + crow;
        #pragma unroll
        for (int ni = 0; ni < 4; ni++) {
            const int j0 = jn0 + wn * 32 + ni * 8 + ccol;
            #pragma unroll
            for (int e = 0; e < 4; e++) {
                const int bb = b0 + (e >> 1) * 8;
                const int jj = j0 + (e & 1);
                const size_t o = (size_t)bb * KU + (size_t)jj * UNITS + u;
                const float v = d[mi][ni][e];
                float4 s4 = *(const float4*)(state + o * 4);
                out[o] = v;
                *(float4*)(out_state + o * 4) = make_float4(v, s4.x, s4.y, s4.z);
            }
        }
    }
}

extern "C" void kernel_launch(void* const* d_in, const int* in_sizes, int n_in,
                              void* d_out, int out_size)
{
    const float* inputs = (const float*)d_in[0];
    const float* state  = (const float*)d_in[1];
    const float* wkern  = (const float*)d_in[2];
    const float* rkern  = (const float*)d_in[3];

    float* out       = (float*)d_out;
    float* out_state = (float*)d_out + (size_t)B_DIM * KU;

    dim3 grid(K_DIM / BN, B_DIM / BM, UNITS);   // (4, 8, 32) = 1024 CTAs
    arma_hmma_kernel<<<grid, 256>>>(inputs, state, wkern, rkern, out, out_state);
}